// round 15
// baseline (speedup 1.0000x reference)
#include <cuda_runtime.h>
#include <cuda_fp16.h>
#include <cstdint>

#define BB 2
#define SS 2048
#define EE 1024
#define NH 16
#define NKV 4
#define HD 64
#define TOKENS (BB*SS)

__device__ float g_Q[TOKENS * NH * HD];
__device__ float g_K[TOKENS * NKV * HD];
__device__ float g_V[TOKENS * NKV * HD];

// fp16 operands, each rounded exactly once from fp32
__device__ __half g_Xh[TOKENS * EE];
__device__ __half g_Wh[1536 * EE];                    // [Wq;Wk;Wv]
__device__ __half g_Ph[EE * EE];                      // Wproj
__device__ __half g_Yh[TOKENS * EE];                  // attention out
__device__ __half g_Qh[TOKENS * NH * HD];             // includes 0.15*log2(e) scale
__device__ __half g_Kh[TOKENS * NKV * HD];
__device__ __half g_Vh[TOKENS * NKV * HD];

// ---- PTX helpers (baseline features only) ----
__device__ __forceinline__ uint32_t smem_u32(const void* p) {
    uint32_t a;
    asm("{ .reg .u64 t; cvta.to.shared.u64 t, %1; cvt.u32.u64 %0, t; }" : "=r"(a) : "l"(p));
    return a;
}
__device__ __forceinline__ void ldsm4(uint32_t r[4], uint32_t a) {
    asm volatile("ldmatrix.sync.aligned.m8n8.x4.shared.b16 {%0,%1,%2,%3}, [%4];"
        : "=r"(r[0]), "=r"(r[1]), "=r"(r[2]), "=r"(r[3]) : "r"(a));
}
__device__ __forceinline__ void ldsm4t(uint32_t r[4], uint32_t a) {
    asm volatile("ldmatrix.sync.aligned.m8n8.x4.trans.shared.b16 {%0,%1,%2,%3}, [%4];"
        : "=r"(r[0]), "=r"(r[1]), "=r"(r[2]), "=r"(r[3]) : "r"(a));
}
__device__ __forceinline__ void mmah(float d[4], const uint32_t a[4], const uint32_t b[2]) {
    asm volatile("mma.sync.aligned.m16n8k16.row.col.f32.f16.f16.f32 "
        "{%0,%1,%2,%3}, {%4,%5,%6,%7}, {%8,%9}, {%0,%1,%2,%3};"
        : "+f"(d[0]), "+f"(d[1]), "+f"(d[2]), "+f"(d[3])
        : "r"(a[0]), "r"(a[1]), "r"(a[2]), "r"(a[3]), "r"(b[0]), "r"(b[1]));
}
__device__ __forceinline__ uint32_t packh(float e, float o) {
    uint32_t r; asm("cvt.rn.f16x2.f32 %0, %1, %2;" : "=r"(r) : "f"(o), "f"(e)); return r;
}
__device__ __forceinline__ float ex2f(float x) {
    float y; asm("ex2.approx.f32 %0, %1;" : "=f"(y) : "f"(x)); return y;
}
__device__ __forceinline__ void cpa16(uint32_t dst, const void* src) {
    asm volatile("cp.async.cg.shared.global [%0], [%1], 16;" :: "r"(dst), "l"(src));
}
#define CP_COMMIT() asm volatile("cp.async.commit_group;" ::: "memory")
#define CP_WAIT(n)  asm volatile("cp.async.wait_group %0;" :: "n"(n) : "memory")

// ---------------------------------------------------------------------------
// All fp32 -> fp16 roundings in ONE launch: X, Wq, Wk, Wv, Wproj.
// ---------------------------------------------------------------------------
__global__ __launch_bounds__(256) void round_all(
    const float* __restrict__ x,
    const float* __restrict__ Wq, const float* __restrict__ Wk,
    const float* __restrict__ Wv, const float* __restrict__ Wp)
{
    int i = blockIdx.x * 256 + threadIdx.x;
    const float* src; __half* dst; size_t off, s4;
    if (i < 1048576)      { src = x;  dst = g_Xh; off = (size_t)i;             s4 = (size_t)i; }
    else if (i < 1310720) { src = Wq; dst = g_Wh; off = (size_t)(i - 1048576); s4 = (size_t)(i - 1048576); }
    else if (i < 1376256) { src = Wk; dst = g_Wh; off = (size_t)(i - 1310720) + 262144; s4 = (size_t)(i - 1310720); }
    else if (i < 1441792) { src = Wv; dst = g_Wh; off = (size_t)(i - 1376256) + 327680; s4 = (size_t)(i - 1376256); }
    else if (i < 1703936) { src = Wp; dst = g_Ph; off = (size_t)(i - 1441792); s4 = (size_t)(i - 1441792); }
    else return;
    float4 v = *(const float4*)(src + s4 * 4);
    __half h[4] = { __float2half(v.x), __float2half(v.y),
                    __float2half(v.z), __float2half(v.w) };
    *(uint2*)(dst + off * 4) = *(uint2*)h;
}

// ---------------------------------------------------------------------------
// fp16 1-pass HMMA GEMM: C = A @ B^T, 128x128 tile, 3-stage cp.async,
// single barrier per K-iteration.
// ---------------------------------------------------------------------------
#define G_AR   10240
#define G_STG  (2 * G_AR)
#define G_SMEM (3 * G_STG)

__device__ __forceinline__ void mma_gemm(
    const __half* __restrict__ A, const __half* __restrict__ B,
    float* __restrict__ Cb, int ldc, int m0)
{
    extern __shared__ char smdyn[];
    uint32_t sb0 = smem_u32(smdyn);

    int t = threadIdx.x;
    int wid = t >> 5, lane = t & 31;
    int wr = wid >> 2, wc = wid & 3;

    const __half* srcs[2] = { A + (size_t)m0 * 1024, B };

    float acc[4][4][4];
    #pragma unroll
    for (int mt = 0; mt < 4; mt++)
        #pragma unroll
        for (int nt = 0; nt < 4; nt++)
            #pragma unroll
            for (int e = 0; e < 4; e++) acc[mt][nt][e] = 0.f;

    #pragma unroll
    for (int s = 0; s < 2; s++) {
        uint32_t base = sb0 + s * G_STG;
        #pragma unroll
        for (int i = 0; i < 4; i++) {
            int c = t + i * 256;
            int arr = c >> 9, cc = c & 511, row = cc >> 2, seg = (cc & 3) * 8;
            cpa16(base + (uint32_t)(arr * G_AR + row * 80 + seg * 2),
                  srcs[arr] + (size_t)row * 1024 + s * 32 + seg);
        }
        CP_COMMIT();
    }

    for (int it = 0; it < 32; it++) {
        if (it + 1 < 32) { CP_WAIT(1); } else { CP_WAIT(0); }
        __syncthreads();

        if (it + 2 < 32) {
            int st = (it + 2) % 3;
            uint32_t base = sb0 + st * G_STG;
            int k0 = (it + 2) * 32;
            #pragma unroll
            for (int i = 0; i < 4; i++) {
                int c = t + i * 256;
                int arr = c >> 9, cc = c & 511, row = cc >> 2, seg = (cc & 3) * 8;
                cpa16(base + (uint32_t)(arr * G_AR + row * 80 + seg * 2),
                      srcs[arr] + (size_t)row * 1024 + k0 + seg);
            }
            CP_COMMIT();
        }

        uint32_t sb = sb0 + (it % 3) * G_STG;
        uint32_t aA = sb, aB = sb + G_AR;

        #pragma unroll
        for (int ks = 0; ks < 2; ks++) {
            int kk = ks * 16;
            uint32_t fA[4][4], fB[4][2];
            int arow = lane & 15;
            int acol = kk + (lane >> 4) * 8;
            #pragma unroll
            for (int mt = 0; mt < 4; mt++) {
                uint32_t off = (uint32_t)((wr * 64 + mt * 16 + arow) * 80 + acol * 2);
                ldsm4(fA[mt], aA + off);
            }
            #pragma unroll
            for (int nt2 = 0; nt2 < 4; nt2 += 2) {
                int ntl = nt2 + (lane >> 4);
                uint32_t bk[4];
                uint32_t off = (uint32_t)((wc * 32 + ntl * 8 + (lane & 7)) * 80
                                          + (kk + (lane & 8)) * 2);
                ldsm4(bk, aB + off);
                fB[nt2][0] = bk[0];     fB[nt2][1] = bk[1];
                fB[nt2+1][0] = bk[2];   fB[nt2+1][1] = bk[3];
            }
            #pragma unroll
            for (int mt = 0; mt < 4; mt++)
                #pragma unroll
                for (int nt = 0; nt < 4; nt++)
                    mmah(acc[mt][nt], fA[mt], fB[nt]);
        }
    }

    #pragma unroll
    for (int mt = 0; mt < 4; mt++)
        #pragma unroll
        for (int nt = 0; nt < 4; nt++) {
            int r0 = m0 + wr * 64 + mt * 16 + (lane >> 2);
            int c0 = wc * 32 + nt * 8 + (lane & 3) * 2;
            float2 w0; w0.x = acc[mt][nt][0]; w0.y = acc[mt][nt][1];
            float2 w1; w1.x = acc[mt][nt][2]; w1.y = acc[mt][nt][3];
            *(float2*)&Cb[(size_t)r0 * ldc + c0]       = w0;
            *(float2*)&Cb[(size_t)(r0 + 8) * ldc + c0] = w1;
        }
}

__global__ __launch_bounds__(256) void qkv_gemm_mma()
{
    int n0 = blockIdx.x * 128;
    int m0 = blockIdx.y * 128;
    float* Cb; int ldc;
    if (n0 < 1024)      { Cb = g_Q + n0;          ldc = 1024; }
    else if (n0 < 1280) { Cb = g_K + (n0 - 1024); ldc = 256;  }
    else                { Cb = g_V + (n0 - 1280); ldc = 256;  }
    mma_gemm(g_Xh, g_Wh + (size_t)n0 * 1024, Cb, ldc, m0);
}

__global__ __launch_bounds__(256) void proj_gemm_mma(float* __restrict__ out)
{
    int n0 = blockIdx.x * 128;
    int m0 = blockIdx.y * 128;
    mma_gemm(g_Yh, g_Ph + (size_t)n0 * 1024, out + n0, 1024, m0);
}

// ---------------------------------------------------------------------------
// Postproc: gate+ve into V, RoPE + RMS-norm on Q/K. Q scale folds in
// 1.2 * 0.125 * log2(e) so attention scores land in the exp2 domain.
// ---------------------------------------------------------------------------
__global__ __launch_bounds__(128) void postproc(
    const float* __restrict__ x, const float* __restrict__ ve,
    const float* __restrict__ cosb, const float* __restrict__ sinb,
    const float* __restrict__ Wgate)
{
    int tok = blockIdx.x;
    int s = tok & (SS - 1);
    int t = threadIdx.x;
    int w = t >> 5;
    int lane = t & 31;

    __shared__ float gate[4];
    __shared__ float x12[12];

    if (t < 12) x12[t] = x[(size_t)tok * EE + t];
    __syncthreads();
    if (t < 4) {
        float acc = 0.f;
        #pragma unroll
        for (int c = 0; c < 12; c++) acc += x12[c] * Wgate[t * 12 + c];
        gate[t] = 3.f / (1.f + __expf(-acc));
    }
    __syncthreads();

    for (int i = t; i < 256; i += 128) {
        int hh = i >> 6;
        float v = g_V[(size_t)tok * 256 + i] + gate[hh] * ve[(size_t)tok * 256 + i];
        g_Vh[(size_t)tok * 256 + i] = __float2half(v);
    }

    const float EPS = 1.1920929e-7f;
    const float LOG2E = 1.44269504088896f;
    float cv = cosb[s * 32 + lane];
    float sv = sinb[s * 32 + lane];

    #pragma unroll
    for (int i = 0; i < 4; i++) {
        int h = w + 4 * i;
        const float* qp = &g_Q[(size_t)tok * 1024 + h * 64];
        float x1 = qp[lane], x2 = qp[lane + 32];
        float r1 =  x1 * cv + x2 * sv;
        float r2 = -x1 * sv + x2 * cv;
        float ss = r1 * r1 + r2 * r2;
        #pragma unroll
        for (int o = 16; o; o >>= 1) ss += __shfl_xor_sync(0xFFFFFFFFu, ss, o);
        float scale = rsqrtf(ss * (1.f / 64.f) + EPS) * (1.2f * 0.125f * LOG2E);
        size_t base = (size_t)tok * 1024 + h * 64;
        g_Qh[base + lane]      = __float2half(r1 * scale);
        g_Qh[base + lane + 32] = __float2half(r2 * scale);
    }
    {
        const float* kp = &g_K[(size_t)tok * 256 + w * 64];
        float x1 = kp[lane], x2 = kp[lane + 32];
        float r1 =  x1 * cv + x2 * sv;
        float r2 = -x1 * sv + x2 * cv;
        float ss = r1 * r1 + r2 * r2;
        #pragma unroll
        for (int o = 16; o; o >>= 1) ss += __shfl_xor_sync(0xFFFFFFFFu, ss, o);
        float scale = rsqrtf(ss * (1.f / 64.f) + EPS) * 1.2f;
        size_t base = (size_t)tok * 256 + w * 64;
        g_Kh[base + lane]      = __float2half(r1 * scale);
        g_Kh[base + lane + 32] = __float2half(r2 * scale);
    }
}

// ---------------------------------------------------------------------------
// Flash attention, fp16, static exp2 softmax. UNPAIRED: one 128-row q-block
// per CTA, grid (16, NH, BB) = 512 CTAs, jblk = 15 - blockIdx.x (LPT order).
// 4-stage cp.async K/V pipeline, one barrier per tile.
// ---------------------------------------------------------------------------
#define A_AR   9216
#define A_STG  (2 * A_AR)       // K + V per stage
#define A_SMEM (4 * A_STG)

__global__ __launch_bounds__(256) void attn_mma()
{
    extern __shared__ char smdyn[];
    uint32_t sb0 = smem_u32(smdyn);

    int jblk = 15 - (int)blockIdx.x;   // big blocks launch first
    int h  = blockIdx.y;
    int b  = blockIdx.z;
    int hkv = h >> 2;
    int t = threadIdx.x;
    int wid = t >> 5, lane = t & 31;

    const float NEGC = -11.5415603272f;     // -8 * log2(e)
    const uint32_t ONES2 = 0x3C003C00u;     // fp16x2 {1.0, 1.0}
    uint32_t bone[2] = { ONES2, ONES2 };

    const __half* srcs[2] = { g_Kh, g_Vh };

    size_t tok0 = (size_t)b * SS + jblk * 128;
    int ntiles = 2 * jblk + 2;

    // ---- stage Q (stage-0 region), build persistent fragments ----
    for (int idx = t; idx < 1024; idx += 256) {
        int row = idx >> 3, ch = (idx & 7) * 8;
        size_t g = (tok0 + row) * 1024 + h * 64 + ch;
        *(uint4*)(smdyn + row * 144 + ch * 2) = *(const uint4*)&g_Qh[g];
    }
    __syncthreads();

    uint32_t qh[4][4];
    {
        int arow = wid * 16 + (lane & 15);
        int acol = (lane >> 4) * 8;
        #pragma unroll
        for (int kc = 0; kc < 4; kc++) {
            uint32_t off = (uint32_t)(arow * 144 + (kc * 16 + acol) * 2);
            ldsm4(qh[kc], sb0 + off);
        }
    }
    __syncthreads();

    float accO[8][4];
    #pragma unroll
    for (int nt = 0; nt < 8; nt++)
        #pragma unroll
        for (int e = 0; e < 4; e++) accO[nt][e] = 0.f;
    float lacc[4] = {0.f, 0.f, 0.f, 0.f};

    // prologue: tiles 0..2 into stages 0..2
    #pragma unroll
    for (int s = 0; s < 3; s++) {
        if (s < ntiles) {
            uint32_t base = sb0 + s * A_STG;
            size_t gb = (size_t)b * SS + s * 64;
            #pragma unroll
            for (int i = 0; i < 4; i++) {
                int c = t + i * 256;
                int arr = c >> 9, cc = c & 511, row = cc >> 3, seg = (cc & 7) * 8;
                cpa16(base + (uint32_t)(arr * A_AR + row * 144 + seg * 2),
                      srcs[arr] + (gb + row) * 256 + hkv * 64 + seg);
            }
            CP_COMMIT();
        }
    }

    for (int kt = 0; kt < ntiles; kt++) {
        // guarantee group kt complete (groups in flight: up to kt+2)
        if (kt + 2 < ntiles)      { CP_WAIT(2); }
        else if (kt + 1 < ntiles) { CP_WAIT(1); }
        else                      { CP_WAIT(0); }
        __syncthreads();

        if (kt + 3 < ntiles) {
            uint32_t base = sb0 + ((kt + 3) & 3) * A_STG;
            size_t gb = (size_t)b * SS + (kt + 3) * 64;
            #pragma unroll
            for (int i = 0; i < 4; i++) {
                int c = t + i * 256;
                int arr = c >> 9, cc = c & 511, row = cc >> 3, seg = (cc & 7) * 8;
                cpa16(base + (uint32_t)(arr * A_AR + row * 144 + seg * 2),
                      srcs[arr] + (gb + row) * 256 + hkv * 64 + seg);
            }
            CP_COMMIT();
        }

        uint32_t sb = sb0 + (kt & 3) * A_STG;
        uint32_t aK = sb, aV = sb + A_AR;

        // ---- S(log2 domain) = Q K^T, accumulator pre-shifted ----
        float sacc[8][4];
        #pragma unroll
        for (int nt = 0; nt < 8; nt++)
            #pragma unroll
            for (int e = 0; e < 4; e++) sacc[nt][e] = NEGC;

        #pragma unroll
        for (int kc = 0; kc < 4; kc++) {
            int kk = kc * 16;
            #pragma unroll
            for (int nt2 = 0; nt2 < 8; nt2 += 2) {
                int ntl = nt2 + (lane >> 4);
                uint32_t bk[4];
                uint32_t off = (uint32_t)((ntl * 8 + (lane & 7)) * 144
                                          + (kk + (lane & 8)) * 2);
                ldsm4(bk, aK + off);
                mmah(sacc[nt2],     qh[kc], bk);
                mmah(sacc[nt2 + 1], qh[kc], bk + 2);
            }
        }

        if (kt >= 2 * jblk) {
            int cb2 = (kt - 2 * jblk) * 64;
            int rloc = wid * 16 + (lane >> 2);
            #pragma unroll
            for (int nt = 0; nt < 8; nt++) {
                int cl = cb2 + nt * 8 + (lane & 3) * 2;
                if (cl     > rloc)     sacc[nt][0] = -1e30f;
                if (cl + 1 > rloc)     sacc[nt][1] = -1e30f;
                if (cl     > rloc + 8) sacc[nt][2] = -1e30f;
                if (cl + 1 > rloc + 8) sacc[nt][3] = -1e30f;
            }
        }

        // ---- p = 2^sacc ----
        #pragma unroll
        for (int nt = 0; nt < 8; nt++) {
            sacc[nt][0] = ex2f(sacc[nt][0]);
            sacc[nt][1] = ex2f(sacc[nt][1]);
            sacc[nt][2] = ex2f(sacc[nt][2]);
            sacc[nt][3] = ex2f(sacc[nt][3]);
        }

        // ---- O += P V ; row sums += P @ ones ----
        #pragma unroll
        for (int kc = 0; kc < 4; kc++) {
            uint32_t ph[4];
            ph[0] = packh(sacc[2*kc][0],   sacc[2*kc][1]);
            ph[1] = packh(sacc[2*kc][2],   sacc[2*kc][3]);
            ph[2] = packh(sacc[2*kc+1][0], sacc[2*kc+1][1]);
            ph[3] = packh(sacc[2*kc+1][2], sacc[2*kc+1][3]);
            mmah(lacc, ph, bone);
            int vrow = kc * 16 + (lane & 15);
            #pragma unroll
            for (int nt2 = 0; nt2 < 8; nt2 += 2) {
                int ntl = nt2 + (lane >> 4);
                uint32_t vv[4];
                uint32_t off = (uint32_t)(vrow * 144 + ntl * 16);
                ldsm4t(vv, aV + off);
                mmah(accO[nt2],     ph, vv);
                mmah(accO[nt2 + 1], ph, vv + 2);
            }
        }
    }

    // ---- epilogue ----
    float inv0 = 1.f / lacc[0], inv1 = 1.f / lacc[2];
    int r0 = wid * 16 + (lane >> 2);
    #pragma unroll
    for (int nt = 0; nt < 8; nt++) {
        int col = h * 64 + nt * 8 + (lane & 3) * 2;
        size_t i0 = (tok0 + r0) * 1024 + col;
        size_t i1 = (tok0 + r0 + 8) * 1024 + col;
        *(uint32_t*)&g_Yh[i0] = packh(accO[nt][0] * inv0, accO[nt][1] * inv0);
        *(uint32_t*)&g_Yh[i1] = packh(accO[nt][2] * inv1, accO[nt][3] * inv1);
    }
}

// ---------------------------------------------------------------------------
extern "C" void kernel_launch(void* const* d_in, const int* in_sizes, int n_in,
                              void* d_out, int out_size)
{
    const float* x     = (const float*)d_in[0];
    const float* ve    = (const float*)d_in[1];
    const float* cosb  = (const float*)d_in[2];
    const float* sinb  = (const float*)d_in[3];
    const float* Wq    = (const float*)d_in[5];
    const float* Wk    = (const float*)d_in[6];
    const float* Wv    = (const float*)d_in[7];
    const float* Wproj = (const float*)d_in[8];
    const float* Wgate = (const float*)d_in[9];
    float* out = (float*)d_out;

    static bool attr_set = false;
    if (!attr_set) {
        cudaFuncSetAttribute(qkv_gemm_mma, cudaFuncAttributeMaxDynamicSharedMemorySize, G_SMEM);
        cudaFuncSetAttribute(proj_gemm_mma, cudaFuncAttributeMaxDynamicSharedMemorySize, G_SMEM);
        cudaFuncSetAttribute(attn_mma, cudaFuncAttributeMaxDynamicSharedMemorySize, A_SMEM);
        attr_set = true;
    }

    round_all<<<1703936 / 256, 256>>>(x, Wq, Wk, Wv, Wproj);

    dim3 g1(12, 32);
    qkv_gemm_mma<<<g1, 256, G_SMEM>>>();

    postproc<<<TOKENS, 128>>>(x, ve, cosb, sinb, Wgate);

    dim3 g3(16, NH, BB);
    attn_mma<<<g3, 256, A_SMEM>>>();

    dim3 g4(8, 32);
    proj_gemm_mma<<<g4, 256, G_SMEM>>>(out);
}

// round 16
// speedup vs baseline: 1.1018x; 1.1018x over previous
#include <cuda_runtime.h>
#include <cuda_fp16.h>
#include <cstdint>

#define BB 2
#define SS 2048
#define EE 1024
#define NH 16
#define NKV 4
#define HD 64
#define TOKENS (BB*SS)

// raw QKV gemm outputs, fp16 (rounded once at the gemm epilogue)
__device__ __half g_Qr[TOKENS * NH * HD];
__device__ __half g_Kr[TOKENS * NKV * HD];
__device__ __half g_Vr[TOKENS * NKV * HD];

// fp16 operands
__device__ __half g_Xh[TOKENS * EE];
__device__ __half g_Wh[1536 * EE];                    // [Wq;Wk;Wv]
__device__ __half g_Ph[EE * EE];                      // Wproj
__device__ __half g_Yh[TOKENS * EE];                  // attention out
__device__ __half g_Qh[TOKENS * NH * HD];             // post-RoPE, incl 0.15*log2e
__device__ __half g_Kh[TOKENS * NKV * HD];
__device__ __half g_Vh[TOKENS * NKV * HD];

// ---- PTX helpers (baseline features only) ----
__device__ __forceinline__ uint32_t smem_u32(const void* p) {
    uint32_t a;
    asm("{ .reg .u64 t; cvta.to.shared.u64 t, %1; cvt.u32.u64 %0, t; }" : "=r"(a) : "l"(p));
    return a;
}
__device__ __forceinline__ void ldsm4(uint32_t r[4], uint32_t a) {
    asm volatile("ldmatrix.sync.aligned.m8n8.x4.shared.b16 {%0,%1,%2,%3}, [%4];"
        : "=r"(r[0]), "=r"(r[1]), "=r"(r[2]), "=r"(r[3]) : "r"(a));
}
__device__ __forceinline__ void ldsm4t(uint32_t r[4], uint32_t a) {
    asm volatile("ldmatrix.sync.aligned.m8n8.x4.trans.shared.b16 {%0,%1,%2,%3}, [%4];"
        : "=r"(r[0]), "=r"(r[1]), "=r"(r[2]), "=r"(r[3]) : "r"(a));
}
__device__ __forceinline__ void mmah(float d[4], const uint32_t a[4], const uint32_t b[2]) {
    asm volatile("mma.sync.aligned.m16n8k16.row.col.f32.f16.f16.f32 "
        "{%0,%1,%2,%3}, {%4,%5,%6,%7}, {%8,%9}, {%0,%1,%2,%3};"
        : "+f"(d[0]), "+f"(d[1]), "+f"(d[2]), "+f"(d[3])
        : "r"(a[0]), "r"(a[1]), "r"(a[2]), "r"(a[3]), "r"(b[0]), "r"(b[1]));
}
__device__ __forceinline__ uint32_t packh(float e, float o) {
    uint32_t r; asm("cvt.rn.f16x2.f32 %0, %1, %2;" : "=r"(r) : "f"(o), "f"(e)); return r;
}
__device__ __forceinline__ float ex2f(float x) {
    float y; asm("ex2.approx.f32 %0, %1;" : "=f"(y) : "f"(x)); return y;
}
__device__ __forceinline__ void cpa16(uint32_t dst, const void* src) {
    asm volatile("cp.async.cg.shared.global [%0], [%1], 16;" :: "r"(dst), "l"(src));
}
#define CP_COMMIT() asm volatile("cp.async.commit_group;" ::: "memory")
#define CP_WAIT(n)  asm volatile("cp.async.wait_group %0;" :: "n"(n) : "memory")

// ---------------------------------------------------------------------------
// All fp32 -> fp16 roundings in ONE launch: X, Wq, Wk, Wv, Wproj.
// ---------------------------------------------------------------------------
__global__ __launch_bounds__(256) void round_all(
    const float* __restrict__ x,
    const float* __restrict__ Wq, const float* __restrict__ Wk,
    const float* __restrict__ Wv, const float* __restrict__ Wp)
{
    int i = blockIdx.x * 256 + threadIdx.x;
    const float* src; __half* dst; size_t off, s4;
    if (i < 1048576)      { src = x;  dst = g_Xh; off = (size_t)i;             s4 = (size_t)i; }
    else if (i < 1310720) { src = Wq; dst = g_Wh; off = (size_t)(i - 1048576); s4 = (size_t)(i - 1048576); }
    else if (i < 1376256) { src = Wk; dst = g_Wh; off = (size_t)(i - 1310720) + 262144; s4 = (size_t)(i - 1310720); }
    else if (i < 1441792) { src = Wv; dst = g_Wh; off = (size_t)(i - 1376256) + 327680; s4 = (size_t)(i - 1376256); }
    else if (i < 1703936) { src = Wp; dst = g_Ph; off = (size_t)(i - 1441792); s4 = (size_t)(i - 1441792); }
    else return;
    float4 v = *(const float4*)(src + s4 * 4);
    __half h[4] = { __float2half(v.x), __float2half(v.y),
                    __float2half(v.z), __float2half(v.w) };
    *(uint2*)(dst + off * 4) = *(uint2*)h;
}

// ---------------------------------------------------------------------------
// fp16 1-pass HMMA GEMM: C = A @ B^T, 128x128 tile, 3-stage cp.async.
// HOUT: write __half (packed pairs); else fp32.
// ---------------------------------------------------------------------------
#define G_AR   10240
#define G_STG  (2 * G_AR)
#define G_SMEM (3 * G_STG)

template<bool HOUT>
__device__ __forceinline__ void mma_gemm(
    const __half* __restrict__ A, const __half* __restrict__ B,
    void* __restrict__ Cb_, int ldc, int m0)
{
    extern __shared__ char smdyn[];
    uint32_t sb0 = smem_u32(smdyn);

    int t = threadIdx.x;
    int wid = t >> 5, lane = t & 31;
    int wr = wid >> 2, wc = wid & 3;

    const __half* srcs[2] = { A + (size_t)m0 * 1024, B };

    float acc[4][4][4];
    #pragma unroll
    for (int mt = 0; mt < 4; mt++)
        #pragma unroll
        for (int nt = 0; nt < 4; nt++)
            #pragma unroll
            for (int e = 0; e < 4; e++) acc[mt][nt][e] = 0.f;

    #pragma unroll
    for (int s = 0; s < 2; s++) {
        uint32_t base = sb0 + s * G_STG;
        #pragma unroll
        for (int i = 0; i < 4; i++) {
            int c = t + i * 256;
            int arr = c >> 9, cc = c & 511, row = cc >> 2, seg = (cc & 3) * 8;
            cpa16(base + (uint32_t)(arr * G_AR + row * 80 + seg * 2),
                  srcs[arr] + (size_t)row * 1024 + s * 32 + seg);
        }
        CP_COMMIT();
    }

    for (int it = 0; it < 32; it++) {
        if (it + 1 < 32) { CP_WAIT(1); } else { CP_WAIT(0); }
        __syncthreads();

        if (it + 2 < 32) {
            int st = (it + 2) % 3;
            uint32_t base = sb0 + st * G_STG;
            int k0 = (it + 2) * 32;
            #pragma unroll
            for (int i = 0; i < 4; i++) {
                int c = t + i * 256;
                int arr = c >> 9, cc = c & 511, row = cc >> 2, seg = (cc & 3) * 8;
                cpa16(base + (uint32_t)(arr * G_AR + row * 80 + seg * 2),
                      srcs[arr] + (size_t)row * 1024 + k0 + seg);
            }
            CP_COMMIT();
        }

        uint32_t sb = sb0 + (it % 3) * G_STG;
        uint32_t aA = sb, aB = sb + G_AR;

        #pragma unroll
        for (int ks = 0; ks < 2; ks++) {
            int kk = ks * 16;
            uint32_t fA[4][4], fB[4][2];
            int arow = lane & 15;
            int acol = kk + (lane >> 4) * 8;
            #pragma unroll
            for (int mt = 0; mt < 4; mt++) {
                uint32_t off = (uint32_t)((wr * 64 + mt * 16 + arow) * 80 + acol * 2);
                ldsm4(fA[mt], aA + off);
            }
            #pragma unroll
            for (int nt2 = 0; nt2 < 4; nt2 += 2) {
                int ntl = nt2 + (lane >> 4);
                uint32_t bk[4];
                uint32_t off = (uint32_t)((wc * 32 + ntl * 8 + (lane & 7)) * 80
                                          + (kk + (lane & 8)) * 2);
                ldsm4(bk, aB + off);
                fB[nt2][0] = bk[0];     fB[nt2][1] = bk[1];
                fB[nt2+1][0] = bk[2];   fB[nt2+1][1] = bk[3];
            }
            #pragma unroll
            for (int mt = 0; mt < 4; mt++)
                #pragma unroll
                for (int nt = 0; nt < 4; nt++)
                    mmah(acc[mt][nt], fA[mt], fB[nt]);
        }
    }

    #pragma unroll
    for (int mt = 0; mt < 4; mt++)
        #pragma unroll
        for (int nt = 0; nt < 4; nt++) {
            int r0 = m0 + wr * 64 + mt * 16 + (lane >> 2);
            int c0 = wc * 32 + nt * 8 + (lane & 3) * 2;
            if (HOUT) {
                __half* Cb = (__half*)Cb_;
                *(uint32_t*)&Cb[(size_t)r0 * ldc + c0] =
                    packh(acc[mt][nt][0], acc[mt][nt][1]);
                *(uint32_t*)&Cb[(size_t)(r0 + 8) * ldc + c0] =
                    packh(acc[mt][nt][2], acc[mt][nt][3]);
            } else {
                float* Cb = (float*)Cb_;
                float2 w0; w0.x = acc[mt][nt][0]; w0.y = acc[mt][nt][1];
                float2 w1; w1.x = acc[mt][nt][2]; w1.y = acc[mt][nt][3];
                *(float2*)&Cb[(size_t)r0 * ldc + c0]       = w0;
                *(float2*)&Cb[(size_t)(r0 + 8) * ldc + c0] = w1;
            }
        }
}

__global__ __launch_bounds__(256) void qkv_gemm_mma()
{
    int n0 = blockIdx.x * 128;
    int m0 = blockIdx.y * 128;
    __half* Cb; int ldc;
    if (n0 < 1024)      { Cb = g_Qr + n0;          ldc = 1024; }
    else if (n0 < 1280) { Cb = g_Kr + (n0 - 1024); ldc = 256;  }
    else                { Cb = g_Vr + (n0 - 1280); ldc = 256;  }
    mma_gemm<true>(g_Xh, g_Wh + (size_t)n0 * 1024, Cb, ldc, m0);
}

__global__ __launch_bounds__(256) void proj_gemm_mma(float* __restrict__ out)
{
    int n0 = blockIdx.x * 128;
    int m0 = blockIdx.y * 128;
    mma_gemm<false>(g_Yh, g_Ph + (size_t)n0 * 1024, out + n0, 1024, m0);
}

// ---------------------------------------------------------------------------
// Postproc: gate+ve into V, RoPE + RMS-norm on Q/K (reads fp16 raw QKV).
// Q scale folds in 1.2 * 0.125 * log2(e).
// ---------------------------------------------------------------------------
__global__ __launch_bounds__(128) void postproc(
    const float* __restrict__ x, const float* __restrict__ ve,
    const float* __restrict__ cosb, const float* __restrict__ sinb,
    const float* __restrict__ Wgate)
{
    int tok = blockIdx.x;
    int s = tok & (SS - 1);
    int t = threadIdx.x;
    int w = t >> 5;
    int lane = t & 31;

    __shared__ float gate[4];
    __shared__ float x12[12];

    if (t < 12) x12[t] = x[(size_t)tok * EE + t];
    __syncthreads();
    if (t < 4) {
        float acc = 0.f;
        #pragma unroll
        for (int c = 0; c < 12; c++) acc += x12[c] * Wgate[t * 12 + c];
        gate[t] = 3.f / (1.f + __expf(-acc));
    }
    __syncthreads();

    for (int i = t; i < 256; i += 128) {
        int hh = i >> 6;
        float v = __half2float(g_Vr[(size_t)tok * 256 + i])
                + gate[hh] * ve[(size_t)tok * 256 + i];
        g_Vh[(size_t)tok * 256 + i] = __float2half(v);
    }

    const float EPS = 1.1920929e-7f;
    const float LOG2E = 1.44269504088896f;
    float cv = cosb[s * 32 + lane];
    float sv = sinb[s * 32 + lane];

    #pragma unroll
    for (int i = 0; i < 4; i++) {
        int h = w + 4 * i;
        const __half* qp = &g_Qr[(size_t)tok * 1024 + h * 64];
        float x1 = __half2float(qp[lane]), x2 = __half2float(qp[lane + 32]);
        float r1 =  x1 * cv + x2 * sv;
        float r2 = -x1 * sv + x2 * cv;
        float ss = r1 * r1 + r2 * r2;
        #pragma unroll
        for (int o = 16; o; o >>= 1) ss += __shfl_xor_sync(0xFFFFFFFFu, ss, o);
        float scale = rsqrtf(ss * (1.f / 64.f) + EPS) * (1.2f * 0.125f * LOG2E);
        size_t base = (size_t)tok * 1024 + h * 64;
        g_Qh[base + lane]      = __float2half(r1 * scale);
        g_Qh[base + lane + 32] = __float2half(r2 * scale);
    }
    {
        const __half* kp = &g_Kr[(size_t)tok * 256 + w * 64];
        float x1 = __half2float(kp[lane]), x2 = __half2float(kp[lane + 32]);
        float r1 =  x1 * cv + x2 * sv;
        float r2 = -x1 * sv + x2 * cv;
        float ss = r1 * r1 + r2 * r2;
        #pragma unroll
        for (int o = 16; o; o >>= 1) ss += __shfl_xor_sync(0xFFFFFFFFu, ss, o);
        float scale = rsqrtf(ss * (1.f / 64.f) + EPS) * 1.2f;
        size_t base = (size_t)tok * 256 + w * 64;
        g_Kh[base + lane]      = __float2half(r1 * scale);
        g_Kh[base + lane + 32] = __float2half(r2 * scale);
    }
}

// ---------------------------------------------------------------------------
// Flash attention (R14 config, best known): fp16, static exp2 softmax,
// ones-mma row sums. Grid (8, NH, BB), 256 threads; CTA does q-blocks
// {15-p, p} (34 tiles). 3-stage cp.async, one barrier per tile.
// ---------------------------------------------------------------------------
#define A_AR   9216
#define A_STG  (2 * A_AR)
#define A_SMEM (3 * A_STG)

__global__ __launch_bounds__(256) void attn_mma()
{
    extern __shared__ char smdyn[];
    uint32_t sb0 = smem_u32(smdyn);

    int p  = blockIdx.x;
    int h  = blockIdx.y;
    int b  = blockIdx.z;
    int hkv = h >> 2;
    int t = threadIdx.x;
    int wid = t >> 5, lane = t & 31;

    const float NEGC = -11.5415603272f;     // -8 * log2(e)
    const uint32_t ONES2 = 0x3C003C00u;
    uint32_t bone[2] = { ONES2, ONES2 };

    const __half* srcs[2] = { g_Kh, g_Vh };

    #pragma unroll 1
    for (int bi = 0; bi < 2; bi++) {
        int jblk = bi ? p : (15 - p);
        size_t tok0 = (size_t)b * SS + jblk * 128;
        int ntiles = 2 * jblk + 2;

        for (int idx = t; idx < 1024; idx += 256) {
            int row = idx >> 3, ch = (idx & 7) * 8;
            size_t g = (tok0 + row) * 1024 + h * 64 + ch;
            *(uint4*)(smdyn + row * 144 + ch * 2) = *(const uint4*)&g_Qh[g];
        }
        __syncthreads();

        uint32_t qh[4][4];
        {
            int arow = wid * 16 + (lane & 15);
            int acol = (lane >> 4) * 8;
            #pragma unroll
            for (int kc = 0; kc < 4; kc++) {
                uint32_t off = (uint32_t)(arow * 144 + (kc * 16 + acol) * 2);
                ldsm4(qh[kc], sb0 + off);
            }
        }
        __syncthreads();

        float accO[8][4];
        #pragma unroll
        for (int nt = 0; nt < 8; nt++)
            #pragma unroll
            for (int e = 0; e < 4; e++) accO[nt][e] = 0.f;
        float lacc[4] = {0.f, 0.f, 0.f, 0.f};

        #pragma unroll
        for (int s = 0; s < 2; s++) {
            if (s < ntiles) {
                uint32_t base = sb0 + s * A_STG;
                size_t gb = (size_t)b * SS + s * 64;
                #pragma unroll
                for (int i = 0; i < 4; i++) {
                    int c = t + i * 256;
                    int arr = c >> 9, cc = c & 511, row = cc >> 3, seg = (cc & 7) * 8;
                    cpa16(base + (uint32_t)(arr * A_AR + row * 144 + seg * 2),
                          srcs[arr] + (gb + row) * 256 + hkv * 64 + seg);
                }
                CP_COMMIT();
            }
        }

        for (int kt = 0; kt < ntiles; kt++) {
            if (kt + 1 < ntiles) { CP_WAIT(1); } else { CP_WAIT(0); }
            __syncthreads();

            if (kt + 2 < ntiles) {
                uint32_t base = sb0 + ((kt + 2) % 3) * A_STG;
                size_t gb = (size_t)b * SS + (kt + 2) * 64;
                #pragma unroll
                for (int i = 0; i < 4; i++) {
                    int c = t + i * 256;
                    int arr = c >> 9, cc = c & 511, row = cc >> 3, seg = (cc & 7) * 8;
                    cpa16(base + (uint32_t)(arr * A_AR + row * 144 + seg * 2),
                          srcs[arr] + (gb + row) * 256 + hkv * 64 + seg);
                }
                CP_COMMIT();
            }

            uint32_t sb = sb0 + (kt % 3) * A_STG;
            uint32_t aK = sb, aV = sb + A_AR;

            float sacc[8][4];
            #pragma unroll
            for (int nt = 0; nt < 8; nt++)
                #pragma unroll
                for (int e = 0; e < 4; e++) sacc[nt][e] = NEGC;

            #pragma unroll
            for (int kc = 0; kc < 4; kc++) {
                int kk = kc * 16;
                #pragma unroll
                for (int nt2 = 0; nt2 < 8; nt2 += 2) {
                    int ntl = nt2 + (lane >> 4);
                    uint32_t bk[4];
                    uint32_t off = (uint32_t)((ntl * 8 + (lane & 7)) * 144
                                              + (kk + (lane & 8)) * 2);
                    ldsm4(bk, aK + off);
                    mmah(sacc[nt2],     qh[kc], bk);
                    mmah(sacc[nt2 + 1], qh[kc], bk + 2);
                }
            }

            if (kt >= 2 * jblk) {
                int cb2 = (kt - 2 * jblk) * 64;
                int rloc = wid * 16 + (lane >> 2);
                #pragma unroll
                for (int nt = 0; nt < 8; nt++) {
                    int cl = cb2 + nt * 8 + (lane & 3) * 2;
                    if (cl     > rloc)     sacc[nt][0] = -1e30f;
                    if (cl + 1 > rloc)     sacc[nt][1] = -1e30f;
                    if (cl     > rloc + 8) sacc[nt][2] = -1e30f;
                    if (cl + 1 > rloc + 8) sacc[nt][3] = -1e30f;
                }
            }

            #pragma unroll
            for (int nt = 0; nt < 8; nt++) {
                sacc[nt][0] = ex2f(sacc[nt][0]);
                sacc[nt][1] = ex2f(sacc[nt][1]);
                sacc[nt][2] = ex2f(sacc[nt][2]);
                sacc[nt][3] = ex2f(sacc[nt][3]);
            }

            #pragma unroll
            for (int kc = 0; kc < 4; kc++) {
                uint32_t ph[4];
                ph[0] = packh(sacc[2*kc][0],   sacc[2*kc][1]);
                ph[1] = packh(sacc[2*kc][2],   sacc[2*kc][3]);
                ph[2] = packh(sacc[2*kc+1][0], sacc[2*kc+1][1]);
                ph[3] = packh(sacc[2*kc+1][2], sacc[2*kc+1][3]);
                mmah(lacc, ph, bone);
                int vrow = kc * 16 + (lane & 15);
                #pragma unroll
                for (int nt2 = 0; nt2 < 8; nt2 += 2) {
                    int ntl = nt2 + (lane >> 4);
                    uint32_t vv[4];
                    uint32_t off = (uint32_t)(vrow * 144 + ntl * 16);
                    ldsm4t(vv, aV + off);
                    mmah(accO[nt2],     ph, vv);
                    mmah(accO[nt2 + 1], ph, vv + 2);
                }
            }
        }

        float inv0 = 1.f / lacc[0], inv1 = 1.f / lacc[2];
        int r0 = wid * 16 + (lane >> 2);
        #pragma unroll
        for (int nt = 0; nt < 8; nt++) {
            int col = h * 64 + nt * 8 + (lane & 3) * 2;
            size_t i0 = (tok0 + r0) * 1024 + col;
            size_t i1 = (tok0 + r0 + 8) * 1024 + col;
            *(uint32_t*)&g_Yh[i0] = packh(accO[nt][0] * inv0, accO[nt][1] * inv0);
            *(uint32_t*)&g_Yh[i1] = packh(accO[nt][2] * inv1, accO[nt][3] * inv1);
        }
        __syncthreads();
    }
}

// ---------------------------------------------------------------------------
extern "C" void kernel_launch(void* const* d_in, const int* in_sizes, int n_in,
                              void* d_out, int out_size)
{
    const float* x     = (const float*)d_in[0];
    const float* ve    = (const float*)d_in[1];
    const float* cosb  = (const float*)d_in[2];
    const float* sinb  = (const float*)d_in[3];
    const float* Wq    = (const float*)d_in[5];
    const float* Wk    = (const float*)d_in[6];
    const float* Wv    = (const float*)d_in[7];
    const float* Wproj = (const float*)d_in[8];
    const float* Wgate = (const float*)d_in[9];
    float* out = (float*)d_out;

    static bool attr_set = false;
    if (!attr_set) {
        cudaFuncSetAttribute(qkv_gemm_mma, cudaFuncAttributeMaxDynamicSharedMemorySize, G_SMEM);
        cudaFuncSetAttribute(proj_gemm_mma, cudaFuncAttributeMaxDynamicSharedMemorySize, G_SMEM);
        cudaFuncSetAttribute(attn_mma, cudaFuncAttributeMaxDynamicSharedMemorySize, A_SMEM);
        attr_set = true;
    }

    round_all<<<1703936 / 256, 256>>>(x, Wq, Wk, Wv, Wproj);

    dim3 g1(12, 32);
    qkv_gemm_mma<<<g1, 256, G_SMEM>>>();

    postproc<<<TOKENS, 128>>>(x, ve, cosb, sinb, Wgate);

    dim3 g3(8, NH, BB);
    attn_mma<<<g3, 256, A_SMEM>>>();

    dim3 g4(8, 32);
    proj_gemm_mma<<<g4, 256, G_SMEM>>>(out);
}